// round 13
// baseline (speedup 1.0000x reference)
#include <cuda_runtime.h>
#include <cstdint>

// x: [B, 64,64,64] f32,  z: [B, P, 3] f32;  B=64, P=4096
// out = concat( suffix-cumsum(hist) [B*G f32],  x * (suffix>0) [B*G f32] )
//
// K1: per-point 18-bit bin code -> g_code (1 MB, overwritten each replay).
// K2: block = (batch, 4-ix slab). 16 KB SMEM u8 histogram built from the
//     batch's 4096 codes (L2-hot), then phase 3 = replica of the round-3
//     loop that sustained 6.5 TB/s: SMEM word -> 16-lane shfl suffix scan
//     -> UNCONDITIONAL coalesced x load -> __stcs counts + rmask.

#define NB     64
#define NP     4096
#define NG     (64 * 64 * 64)
#define NTOT   (NB * NG)
#define SLABS  16                          // 4 ix values per slab
#define SLAB_BINS (4 * 64 * 64)            // 16384 bins per block
#define SLAB_W    (SLAB_BINS / 4)          // 4096 u32 words (16 KB)
#define THREADS 256

__device__ unsigned int g_code[NB * NP];   // 1 MB

// ---------------------------------------------------------------------------
// K1: compute linear bin code per point. 1 thread/point, fully coalesced.
// ---------------------------------------------------------------------------
__global__ void k_code(const float* __restrict__ z) {
    int t = blockIdx.x * blockDim.x + threadIdx.x;
    if (t >= NB * NP) return;
    float zx = z[3 * t + 0];
    float zy = z[3 * t + 1];
    float zz = z[3 * t + 2];
    int ix = (int)(zx * 64.0f); ix = ix < 0 ? 0 : (ix > 63 ? 63 : ix);
    int iy = (int)(zy * 64.0f); iy = iy < 0 ? 0 : (iy > 63 ? 63 : iy);
    int iz = (int)(zz * 64.0f); iz = iz < 0 ? 0 : (iz > 63 ? 63 : iz);
    g_code[t] = (unsigned int)(ix * 4096 + iy * 64 + iz);
}

// ---------------------------------------------------------------------------
// K2: fused SMEM histogram + suffix scan + mask-multiply.
// ---------------------------------------------------------------------------
__global__ void __launch_bounds__(THREADS)
k_fused(const float4* __restrict__ x,
        float4* __restrict__ counts,
        float4* __restrict__ rmask) {
    __shared__ unsigned int hist[SLAB_W];          // 16 KB: u8 bins, 4/word

    int blk  = blockIdx.x;                         // 0 .. NB*SLABS-1
    int b    = blk >> 4;                           // batch
    int slab = blk & 15;                           // 4-ix slab
    int tid  = threadIdx.x;

    // Phase 1: zero SMEM hist (16 words per thread).
    #pragma unroll
    for (int k = 0; k < SLAB_W / THREADS; k++)
        hist[tid + k * THREADS] = 0u;
    __syncthreads();

    // Phase 2: scan this batch's 4096 codes; bin those in our slab.
    const unsigned int* cb = g_code + b * NP;
    #pragma unroll
    for (int k = 0; k < NP / THREADS; k++) {
        unsigned int code = cb[tid + k * THREADS];
        if ((int)(code >> 14) == slab) {           // avg 1 match per thread
            unsigned int bin = code & 16383u;
            atomicAdd(&hist[bin >> 2], 1u << (8u * (bin & 3u)));
        }
    }
    __syncthreads();

    // Phase 3: streaming output loop (round-3 structure, 6.5 TB/s proven).
    int g4_base = b * (NG / 4) + slab * SLAB_W;
    #pragma unroll 4
    for (int k = 0; k < SLAB_W / THREADS; k++) {
        int c  = tid + k * THREADS;                // 0 .. 4095
        int g4 = g4_base + c;
        int lane16 = c & 15;                       // position within 64-row

        unsigned int hw = hist[c];
        float4 xr = x[g4];                         // UNCONDITIONAL, coalesced

        float c0 = (float)( hw        & 0xffu);
        float c1 = (float)((hw >> 8)  & 0xffu);
        float c2 = (float)((hw >> 16) & 0xffu);
        float c3 = (float)((hw >> 24) & 0xffu);

        // 16-lane suffix scan of per-word sums (warp = 2 aligned rows).
        float v = c0 + c1 + c2 + c3;
        #pragma unroll
        for (int off = 1; off < 16; off <<= 1) {
            float t = __shfl_down_sync(0xffffffffu, v, off, 16);
            if (lane16 + off < 16) v += t;
        }
        float o0 = v;
        float o1 = o0 - c0;
        float o2 = o1 - c1;
        float o3 = o2 - c2;

        __stcs(&counts[g4], make_float4(o0, o1, o2, o3));
        __stcs(&rmask[g4],  make_float4(o0 > 0.f ? xr.x : 0.f,
                                        o1 > 0.f ? xr.y : 0.f,
                                        o2 > 0.f ? xr.z : 0.f,
                                        o3 > 0.f ? xr.w : 0.f));
    }
}

// ---------------------------------------------------------------------------
extern "C" void kernel_launch(void* const* d_in, const int* in_sizes, int n_in,
                              void* d_out, int out_size) {
    const float* x = (const float*)d_in[0];
    const float* z = (const float*)d_in[1];

    float* counts = (float*)d_out;
    float* rmask  = (float*)d_out + (size_t)NTOT;

    {
        int n = NB * NP;
        k_code<<<(n + 255) / 256, 256>>>(z);
    }
    k_fused<<<NB * SLABS, THREADS>>>((const float4*)x,
                                     (float4*)counts, (float4*)rmask);
}

// round 14
// speedup vs baseline: 1.2772x; 1.2772x over previous
#include <cuda_runtime.h>
#include <cstdint>

// x: [B, 64,64,64] f32,  z: [B, P, 3] f32;  B=64, P=4096
// out = concat( suffix-cumsum(hist) [B*G f32],  x * (suffix>0) [B*G f32] )
//
// Per (b,ix,iy)-row (262,144 rows, length-64 along iz) ONE uint4 in g_rows:
//   bytes 0..11 : iz of up to 12 points (u8 each; P(count>12) ~ 1e-10)
//   word  3     : point count (atomicAdd target; reset by K3 -> replay-safe)
// Byte stores touch only words 0..2; the atomic RMW touches only word 3:
// no write race. suffix[row][p] = #{ stored iz >= p } — order independent.

#define NB    64
#define NP    4096
#define NG    (64 * 64 * 64)
#define NTOT  (NB * NG)
#define NROWS (NB * 64 * 64)
#define SLOTS 12

__device__ __align__(16) unsigned int g_rows[NROWS * 4];   // 4 MB

// ---------------------------------------------------------------------------
// K2: scatter points into per-row slot lists. One thread per point.
// ---------------------------------------------------------------------------
__global__ void k_scatter(const float* __restrict__ z) {
    int t = blockIdx.x * blockDim.x + threadIdx.x;
    if (t >= NB * NP) return;
    float zx = z[3 * t + 0];
    float zy = z[3 * t + 1];
    float zz = z[3 * t + 2];
    int ix = (int)(zx * 64.0f); ix = ix < 0 ? 0 : (ix > 63 ? 63 : ix);
    int iy = (int)(zy * 64.0f); iy = iy < 0 ? 0 : (iy > 63 ? 63 : iy);
    int iz = (int)(zz * 64.0f); iz = iz < 0 ? 0 : (iz > 63 ? 63 : iz);
    int b  = t >> 12;
    unsigned int row = (unsigned int)b * 4096u + (unsigned int)ix * 64u + (unsigned int)iy;

    unsigned int s = atomicAdd(&g_rows[row * 4 + 3], 1u);   // counter word
    if (s < SLOTS)
        ((unsigned char*)g_rows)[row * 16 + s] = (unsigned char)iz;
}

// Sentinel-masked SIMD suffix compare for one 4-byte slot word.
// Invalid bytes -> 0x80 (-128 signed): never >= any threshold 0..66.
__device__ __forceinline__ void acc_word(unsigned int w, int valid,
                                         unsigned int t0, unsigned int t1,
                                         unsigned int t2, unsigned int t3,
                                         int& o0, int& o1, int& o2, int& o3) {
    valid = valid < 0 ? 0 : (valid > 4 ? 4 : valid);
    unsigned int vm = (unsigned int)((1ull << (8 * valid)) - 1ull);
    unsigned int wv = (w & vm) | (0x80808080u & ~vm);
    o0 += __popc(__vcmpges4(wv, t0));
    o1 += __popc(__vcmpges4(wv, t1));
    o2 += __popc(__vcmpges4(wv, t2));
    o3 += __popc(__vcmpges4(wv, t3));
}

// ---------------------------------------------------------------------------
// K3: fused suffix-count + mask-multiply + counter reset (round-4 structure,
// the measured-best family). 16 lanes/row, one float4 chunk each.
// Single uint4 load per row carries both slots and count.
// ---------------------------------------------------------------------------
__global__ void __launch_bounds__(256, 8)
k_suffix(const float4* __restrict__ x,
         float4* __restrict__ counts,
         float4* __restrict__ rmask) {
    int g = blockIdx.x * blockDim.x + threadIdx.x;   // 0 .. NTOT/4-1
    if (g >= NTOT / 4) return;
    int row = g >> 4;
    int l16 = g & 15;

    uint4 sa = *((const uint4*)g_rows + row);        // slots + count, one LDG
    int n_raw = (int)sa.w;
    int n = n_raw > SLOTS ? SLOTS : n_raw;

    int p0 = l16 * 4;
    unsigned int t0 = (unsigned int)p0 * 0x01010101u;
    unsigned int t1 = t0 + 0x01010101u;
    unsigned int t2 = t1 + 0x01010101u;
    unsigned int t3 = t2 + 0x01010101u;
    int o0 = 0, o1 = 0, o2 = 0, o3 = 0;

    acc_word(sa.x, n, t0, t1, t2, t3, o0, o1, o2, o3);
    if (n > 4) {                                     // rare (~0.4% of rows)
        acc_word(sa.y, n - 4, t0, t1, t2, t3, o0, o1, o2, o3);
        acc_word(sa.z, n - 8, t0, t1, t2, t3, o0, o1, o2, o3);
    }
    o0 >>= 3; o1 >>= 3; o2 >>= 3; o3 >>= 3;          // 8 set bits per match

    // reset counter word for the next graph replay (all lanes read already)
    if (l16 == 0 && n_raw != 0) g_rows[row * 4 + 3] = 0u;

    // counts store independent of x -> issue before the predicated load
    __stcs(&counts[g], make_float4((float)o0, (float)o1, (float)o2, (float)o3));

    // Divergent predicated x load (round-4 style: measured best).
    float4 rm = make_float4(0.f, 0.f, 0.f, 0.f);
    if (o0 > 0) {                                    // suffix monotone: o0 max
        float4 xr = x[g];
        rm.x = xr.x;
        if (o1 > 0) rm.y = xr.y;
        if (o2 > 0) rm.z = xr.z;
        if (o3 > 0) rm.w = xr.w;
    }
    __stcs(&rmask[g], rm);
}

// ---------------------------------------------------------------------------
extern "C" void kernel_launch(void* const* d_in, const int* in_sizes, int n_in,
                              void* d_out, int out_size) {
    const float* x = (const float*)d_in[0];
    const float* z = (const float*)d_in[1];

    float* counts = (float*)d_out;
    float* rmask  = (float*)d_out + (size_t)NTOT;

    {
        int n = NB * NP;
        k_scatter<<<(n + 255) / 256, 256>>>(z);
    }
    {
        int n = NTOT / 4;
        k_suffix<<<(n + 255) / 256, 256>>>((const float4*)x,
                                           (float4*)counts, (float4*)rmask);
    }
}